// round 14
// baseline (speedup 1.0000x reference)
#include <cuda_runtime.h>
#include <stdint.h>

// DisplaceChannel: out[b,c,y,x] = inp[b,c, y-off_y[p], x-off_x[p]] (p = c/32),
// zero where source out of [0,64). Offsets multiples of 32 -> float4 vectors
// uniformly valid/invalid, 16B alignment preserved.
//
// FINAL — memory-system floor (~15.5us kernel) confirmed across 15 variants:
// LDG.128 / 256-bit ld-st / TMA bulk all converge here; every policy away
// from streaming stores (evict_normal, evict_last full & zeros-only,
// write-through) and every scheduling deviation (MLP=8, multi-plane blocks,
// single-wave grid) regresses 2-4us. Harness rules ban the only remaining
// levers (L2 persistence carveout, cross-replay store elision).
//
// Shape: grid (CH,B) = 4608 blocks, one 64x64 plane each; 256 threads x
// 4 float4; loads front-batched (MLP=4); __stcs streaming stores keep the
// 33.6MB valid input read set L2-resident across graph replays. Zero-vector
// stores (5/9 of output) are issued before the load scoreboard clears —
// they depend on nothing, so the DRAM write drain starts immediately.

#define CH 288          // 9 * 32
#define H 64
#define W 64
#define W4 16           // float4 per row
#define PLANE4 1024     // H * W4

__global__ __launch_bounds__(256)
void displace_kernel(const float4* __restrict__ in,
                     const int* __restrict__ offsets,
                     float4* __restrict__ out)
{
    const int c = blockIdx.x;          // 0..287
    const int b = blockIdx.y;          // 0..15
    const int p = c >> 5;              // position 0..8

    const int off_x = __ldg(&offsets[2 * p]);
    const int off_y = __ldg(&offsets[2 * p + 1]);

    const long base = ((long)b * CH + c) * PLANE4;
    const float4* __restrict__ src = in + base;
    float4* __restrict__ dst = out + base;

    const int t = threadIdx.x;
    const float4 zero = make_float4(0.f, 0.f, 0.f, 0.f);

    float4 v[4];
    bool valid[4];

    // Phase 1: front-batched loads (MLP=4) + dependency-free zero stores.
#pragma unroll
    for (int j = 0; j < 4; j++) {
        const int vid = t + (j << 8);
        const int x4 = vid & (W4 - 1);
        const int y  = vid >> 4;
        const int sy = y - off_y;
        const int sx = (x4 << 2) - off_x;
        valid[j] = ((unsigned)sy < H) & ((unsigned)sx < W);
        if (valid[j]) {
            v[j] = __ldg(&src[(sy << 4) + (sx >> 2)]);
        } else {
            __stcs(&dst[vid], zero);           // drain starts immediately
        }
    }

    // Phase 2: stores that depend on the loads.
#pragma unroll
    for (int j = 0; j < 4; j++) {
        if (valid[j]) {
            __stcs(&dst[t + (j << 8)], v[j]);  // stream output past L2
        }
    }
}

extern "C" void kernel_launch(void* const* d_in, const int* in_sizes, int n_in,
                              void* d_out, int out_size)
{
    const float4* in = (const float4*)d_in[0];
    const int* offsets = (const int*)d_in[1];
    float4* out = (float4*)d_out;

    dim3 grid(CH, 16);   // (channels, batch) = 4608 blocks
    displace_kernel<<<grid, 256>>>(in, offsets, out);
}

// round 15
// speedup vs baseline: 1.1505x; 1.1505x over previous
#include <cuda_runtime.h>
#include <stdint.h>

// DisplaceChannel: out[b,c,y,x] = inp[b,c, y-off_y[p], x-off_x[p]] (p = c/32),
// zero where source out of [0,64). Offsets are multiples of 32 -> float4
// vectors uniformly valid/invalid, 16B alignment preserved.
//
// FINAL — exact R2 binary, best measured record (14.82 / 14.85 / 15.97 us
// across three runs). Memory-system floor confirmed across 16 variants:
// LDG.128 / 256-bit ld-st / TMA bulk all converge to ~15.5us kernel time;
// every deviation (MLP=8, multi-plane blocks, single-wave grid, evict_normal,
// evict_last full & zeros-only, write-through, early-zero-store reordering)
// is neutral-to-worse. Harness rules ban the remaining levers (L2
// persistence carveout, cross-replay store elision).
//
// Shape: grid (CH,B) = 4608 blocks, one 64x64 plane each; 256 threads x
// 4 float4; loads front-batched (MLP=4); __stcs streaming stores keep the
// 33.6MB valid input read set L2-resident across graph replays.

#define CH 288          // 9 * 32
#define H 64
#define W 64
#define W4 16           // float4 per row
#define PLANE4 1024     // H * W4

__global__ __launch_bounds__(256)
void displace_kernel(const float4* __restrict__ in,
                     const int* __restrict__ offsets,
                     float4* __restrict__ out)
{
    const int c = blockIdx.x;          // 0..287
    const int b = blockIdx.y;          // 0..15
    const int p = c >> 5;              // position 0..8

    const int off_x = __ldg(&offsets[2 * p]);
    const int off_y = __ldg(&offsets[2 * p + 1]);

    const long base = ((long)b * CH + c) * PLANE4;
    const float4* __restrict__ src = in + base;
    float4* __restrict__ dst = out + base;

    const int t = threadIdx.x;

    float4 v[4];
#pragma unroll
    for (int j = 0; j < 4; j++) {
        const int vid = t + (j << 8);
        const int x4 = vid & (W4 - 1);
        const int y  = vid >> 4;
        const int sy = y - off_y;
        const int sx = (x4 << 2) - off_x;
        v[j] = make_float4(0.f, 0.f, 0.f, 0.f);
        if ((unsigned)sy < H && (unsigned)sx < W) {
            v[j] = __ldg(&src[(sy << 4) + (sx >> 2)]);
        }
    }
#pragma unroll
    for (int j = 0; j < 4; j++) {
        __stcs(&dst[t + (j << 8)], v[j]);   // stream output past L2
    }
}

extern "C" void kernel_launch(void* const* d_in, const int* in_sizes, int n_in,
                              void* d_out, int out_size)
{
    const float4* in = (const float4*)d_in[0];
    const int* offsets = (const int*)d_in[1];
    float4* out = (float4*)d_out;

    dim3 grid(CH, 16);   // (channels, batch) = 4608 blocks
    displace_kernel<<<grid, 256>>>(in, offsets, out);
}